// round 7
// baseline (speedup 1.0000x reference)
#include <cuda_runtime.h>

#define BATCH 32
#define IN_H  128
#define IN_W  512
#define CHAN  32
#define OUT_H 64
#define OUT_W 256

// Each thread: one float4 channel-group (cg) for FOUR output points
// (b, hy+16k, wx), k=0..3. Structure: all 16 gather loads issued before
// any consumption -> MLP ~16 per thread.
// Threads = 32*64*256*8/4 = 1,048,576 -> 4096 blocks of 256.

__global__ void __launch_bounds__(256)
stn_bilinear_kernel(const float* __restrict__ image,
                    const float* __restrict__ theta,
                    float* __restrict__ out)
{
    const unsigned t  = blockIdx.x * 256u + threadIdx.x;
    const unsigned cg = t & 7u;          // channel group 0..7
    const unsigned n  = t >> 3;
    const unsigned wx = n & 255u;        // OUT_W = 256
    const unsigned r  = n >> 8;
    const unsigned hy = r & 15u;         // 0..15 (points at hy+16k)
    const unsigned b  = r >> 4;          // 0..31

    const float xg = (float)wx * (2.0f / 255.0f) - 1.0f;

    // theta[b] as 2x3; reference hack: zero row 1 of batch 0, row 0 of batch 1
    const float* th = theta + b * 6u;
    float t00 = __ldg(th + 0), t01 = __ldg(th + 1), t02 = __ldg(th + 2);
    float t10 = __ldg(th + 3), t11 = __ldg(th + 4), t12 = __ldg(th + 5);
    if (b == 0u) { t10 = 0.0f; t11 = 0.0f; t12 = 0.0f; }
    if (b == 1u) { t00 = 0.0f; t01 = 0.0f; t02 = 0.0f; }

    const float cxb = t00 * xg + t02;     // x-part independent of yg
    const float cyb = t10 * xg + t12;

    const float4* __restrict__ img4 = (const float4*)image;
    float4* __restrict__ out4 = (float4*)out;
    const unsigned basePix = b * (unsigned)(IN_H * IN_W);

    // ---- Phase 1: per-point index + weight computation (no memory) ----
    float wA[4], wB[4], wC[4], wD[4];
    unsigned iA[4], iB[4], iC[4], iD[4];

    #pragma unroll
    for (int k = 0; k < 4; ++k) {
        const float yg = (float)(hy + 16u * k) * (2.0f / 63.0f) - 1.0f;

        float cx = t01 * yg + cxb;
        float cy = t11 * yg + cyb;

        float x = 0.5f * (cx + 1.0f) * (float)IN_W;   // uses W, not W-1
        float y = 0.5f * (cy + 1.0f) * (float)IN_H;

        int x0 = (int)x;                               // trunc toward zero
        int y0 = (int)y;
        int x1 = x0 + 1;
        int y1 = y0 + 1;
        x0 = min(max(x0, 0), IN_W - 1);               // clip BEFORE weights
        x1 = min(max(x1, 0), IN_W - 1);
        y0 = min(max(y0, 0), IN_H - 1);
        y1 = min(max(y1, 0), IN_H - 1);

        float x0f = (float)x0, x1f = (float)x1;
        float y0f = (float)y0, y1f = (float)y1;

        wA[k] = (x1f - x) * (y1f - y);
        wB[k] = (x1f - x) * (y - y0f);
        wC[k] = (x - x0f) * (y1f - y);
        wD[k] = (x - x0f) * (y - y0f);

        const unsigned row0 = basePix + (unsigned)y0 * (unsigned)IN_W;
        const unsigned row1 = basePix + (unsigned)y1 * (unsigned)IN_W;
        iA[k] = ((row0 + (unsigned)x0) << 3) + cg;
        iB[k] = ((row1 + (unsigned)x0) << 3) + cg;
        iC[k] = ((row0 + (unsigned)x1) << 3) + cg;
        iD[k] = ((row1 + (unsigned)x1) << 3) + cg;
    }

    // ---- Phase 2: issue ALL 16 gathers back-to-back (max MLP) ----
    float4 pA[4], pB[4], pC[4], pD[4];
    #pragma unroll
    for (int k = 0; k < 4; ++k) pA[k] = __ldg(img4 + iA[k]);
    #pragma unroll
    for (int k = 0; k < 4; ++k) pB[k] = __ldg(img4 + iB[k]);
    #pragma unroll
    for (int k = 0; k < 4; ++k) pC[k] = __ldg(img4 + iC[k]);
    #pragma unroll
    for (int k = 0; k < 4; ++k) pD[k] = __ldg(img4 + iD[k]);

    // ---- Phase 3: blend + store (consume in issue order) ----
    const unsigned oBase = ((b * (unsigned)OUT_H + hy) * (unsigned)OUT_W + wx) * 8u + cg;
    #pragma unroll
    for (int k = 0; k < 4; ++k) {
        float4 res;
        res.x = pA[k].x * wA[k] + pB[k].x * wB[k] + pC[k].x * wC[k] + pD[k].x * wD[k];
        res.y = pA[k].y * wA[k] + pB[k].y * wB[k] + pC[k].y * wC[k] + pD[k].y * wD[k];
        res.z = pA[k].z * wA[k] + pB[k].z * wB[k] + pC[k].z * wC[k] + pD[k].z * wD[k];
        res.w = pA[k].w * wA[k] + pB[k].w * wB[k] + pC[k].w * wC[k] + pD[k].w * wD[k];
        out4[oBase + (unsigned)k * (16u * OUT_W * 8u)] = res;
    }
}

extern "C" void kernel_launch(void* const* d_in, const int* in_sizes, int n_in,
                              void* d_out, int out_size)
{
    const float* image = (const float*)d_in[0];
    const float* theta = (const float*)d_in[1];
    float*       out   = (float*)d_out;

    const unsigned total_threads = (unsigned)BATCH * OUT_H * OUT_W * (CHAN / 4) / 4u;
    stn_bilinear_kernel<<<total_threads / 256u, 256>>>(image, theta, out);
}

// round 8
// speedup vs baseline: 1.1722x; 1.1722x over previous
#include <cuda_runtime.h>

#define BATCH 32
#define IN_H  128
#define IN_W  512
#define CHAN  32
#define OUT_H 64
#define OUT_W 256

// 2 output points per thread (hy and hy+32), 8 threads per point (float4 per
// thread). __launch_bounds__(256, 8) caps registers at 32 -> 8 CTAs/SM ->
// 100% theoretical occupancy, combining R3's low instruction count with R1's
// latency hiding. Threads = 2,097,152 -> 8192 blocks of 256.

__global__ void __launch_bounds__(256, 8)
stn_bilinear_kernel(const float* __restrict__ image,
                    const float* __restrict__ theta,
                    float* __restrict__ out)
{
    const unsigned t  = blockIdx.x * 256u + threadIdx.x;
    const unsigned cg = t & 7u;          // channel group 0..7
    const unsigned n  = t >> 3;
    const unsigned wx = n & 255u;        // OUT_W = 256
    const unsigned r  = n >> 8;
    const unsigned hy = r & 31u;         // 0..31 (second point = hy+32)
    const unsigned b  = r >> 5;          // 0..31

    const float xg  = (float)wx * (2.0f / 255.0f) - 1.0f;
    const float yg0 = (float)hy * (2.0f / 63.0f) - 1.0f;
    const float yg1 = (float)(hy + 32u) * (2.0f / 63.0f) - 1.0f;

    // theta[b] as 2x3; reference hack: zero row 1 of batch 0, row 0 of batch 1
    const float* th = theta + b * 6u;
    float t00 = __ldg(th + 0), t01 = __ldg(th + 1), t02 = __ldg(th + 2);
    float t10 = __ldg(th + 3), t11 = __ldg(th + 4), t12 = __ldg(th + 5);
    if (b == 0u) { t10 = 0.0f; t11 = 0.0f; t12 = 0.0f; }
    if (b == 1u) { t00 = 0.0f; t01 = 0.0f; t02 = 0.0f; }

    const float cxb = t00 * xg + t02;   // parts independent of yg
    const float cyb = t10 * xg + t12;

    const float4* __restrict__ img4 = (const float4*)image;
    float4* __restrict__ out4 = (float4*)out;
    const unsigned basePix = b * (unsigned)(IN_H * IN_W);
    const unsigned oBase   = ((b * (unsigned)OUT_H + hy) * (unsigned)OUT_W + wx) * 8u + cg;

    #pragma unroll
    for (int half = 0; half < 2; ++half) {
        const float yg = half ? yg1 : yg0;

        float cx = t01 * yg + cxb;
        float cy = t11 * yg + cyb;

        float x = 0.5f * (cx + 1.0f) * (float)IN_W;   // uses W, not W-1
        float y = 0.5f * (cy + 1.0f) * (float)IN_H;

        int x0 = (int)x;                              // trunc toward zero
        int y0 = (int)y;
        int x1 = x0 + 1;
        int y1 = y0 + 1;
        x0 = min(max(x0, 0), IN_W - 1);               // clip BEFORE weights
        x1 = min(max(x1, 0), IN_W - 1);
        y0 = min(max(y0, 0), IN_H - 1);
        y1 = min(max(y1, 0), IN_H - 1);

        float x0f = (float)x0, x1f = (float)x1;
        float y0f = (float)y0, y1f = (float)y1;

        float wA = (x1f - x) * (y1f - y);
        float wB = (x1f - x) * (y - y0f);
        float wC = (x - x0f) * (y1f - y);
        float wD = (x - x0f) * (y - y0f);

        const unsigned row0 = basePix + (unsigned)y0 * (unsigned)IN_W;
        const unsigned row1 = basePix + (unsigned)y1 * (unsigned)IN_W;

        float4 pA = __ldg(img4 + (((row0 + (unsigned)x0) << 3) + cg));
        float4 pB = __ldg(img4 + (((row1 + (unsigned)x0) << 3) + cg));
        float4 pC = __ldg(img4 + (((row0 + (unsigned)x1) << 3) + cg));
        float4 pD = __ldg(img4 + (((row1 + (unsigned)x1) << 3) + cg));

        float4 res;
        res.x = pA.x * wA + pB.x * wB + pC.x * wC + pD.x * wD;
        res.y = pA.y * wA + pB.y * wB + pC.y * wC + pD.y * wD;
        res.z = pA.z * wA + pB.z * wB + pC.z * wC + pD.z * wD;
        res.w = pA.w * wA + pB.w * wB + pC.w * wC + pD.w * wD;

        out4[oBase + (unsigned)half * (32u * OUT_W * 8u)] = res;
    }
}

extern "C" void kernel_launch(void* const* d_in, const int* in_sizes, int n_in,
                              void* d_out, int out_size)
{
    const float* image = (const float*)d_in[0];
    const float* theta = (const float*)d_in[1];
    float*       out   = (float*)d_out;

    const unsigned total_threads = (unsigned)BATCH * OUT_H * OUT_W * (CHAN / 4) / 2u;
    stn_bilinear_kernel<<<total_threads / 256u, 256>>>(image, theta, out);
}